// round 1
// baseline (speedup 1.0000x reference)
#include <cuda_runtime.h>
#include <cuda_bf16.h>
#include <math.h>

// Problem constants
#define BSZ 2
#define SEQ 2048
#define HID 4096
#define NH  32
#define NKV 8
#define HD  128
#define ROWS (BSZ*SEQ)           // 4096

// ---------------- scratch (device globals; no allocation allowed) ----------------
__device__ float g_Q[(size_t)ROWS * HID];        // 4096 x 4096
__device__ float g_K[(size_t)ROWS * (NKV*HD)];   // 4096 x 1024
__device__ float g_V[(size_t)ROWS * (NKV*HD)];   // 4096 x 1024
__device__ float g_O[(size_t)ROWS * HID];        // 4096 x 4096

// ---------------- SGEMM: C[M,N] = A[M,K] @ B[K,N], row-major fp32 ----------------
// 128x128 block tile, BK=16, 8x8 per thread, 256 threads.
#define GBM 128
#define GBN 128
#define GBK 16
#define GTM 8
#define GTN 8

__global__ __launch_bounds__(256)
void sgemm_kernel(const float* __restrict__ A, const float* __restrict__ B,
                  float* __restrict__ C, int M, int N, int K) {
    __shared__ float As[GBK][GBM];   // transposed A tile
    __shared__ float Bs[GBK][GBN];

    const int tid = threadIdx.x;
    const int bm = blockIdx.y * GBM;
    const int bn = blockIdx.x * GBN;

    // A load mapping: 128 rows x 4 float4 per row = 512 float4; 2 per thread
    const int aRow = tid >> 2;          // 0..63
    const int aCol = (tid & 3) * 4;     // 0,4,8,12
    // B load mapping: 16 rows x 32 float4 per row = 512 float4; 2 per thread
    const int bRow = tid >> 5;          // 0..7
    const int bCol = (tid & 31) * 4;

    const int tr = (tid >> 4) * GTM;    // 0..120
    const int tc = (tid & 15) * GTN;

    float acc[GTM][GTN];
#pragma unroll
    for (int i = 0; i < GTM; i++)
#pragma unroll
        for (int j = 0; j < GTN; j++) acc[i][j] = 0.0f;

    for (int k0 = 0; k0 < K; k0 += GBK) {
#pragma unroll
        for (int r = 0; r < 2; r++) {
            int row = aRow + r * 64;
            float4 v = *(const float4*)&A[(size_t)(bm + row) * K + k0 + aCol];
            As[aCol + 0][row] = v.x;
            As[aCol + 1][row] = v.y;
            As[aCol + 2][row] = v.z;
            As[aCol + 3][row] = v.w;
        }
#pragma unroll
        for (int r = 0; r < 2; r++) {
            int row = bRow + r * 8;
            *(float4*)&Bs[row][bCol] = *(const float4*)&B[(size_t)(k0 + row) * N + bn + bCol];
        }
        __syncthreads();

#pragma unroll
        for (int k = 0; k < GBK; k++) {
            float4 a0 = *(const float4*)&As[k][tr];
            float4 a1 = *(const float4*)&As[k][tr + 4];
            float4 b0 = *(const float4*)&Bs[k][tc];
            float4 b1 = *(const float4*)&Bs[k][tc + 4];
            float ra[GTM] = {a0.x, a0.y, a0.z, a0.w, a1.x, a1.y, a1.z, a1.w};
            float rb[GTN] = {b0.x, b0.y, b0.z, b0.w, b1.x, b1.y, b1.z, b1.w};
#pragma unroll
            for (int i = 0; i < GTM; i++)
#pragma unroll
                for (int j = 0; j < GTN; j++)
                    acc[i][j] = fmaf(ra[i], rb[j], acc[i][j]);
        }
        __syncthreads();
    }

#pragma unroll
    for (int i = 0; i < GTM; i++) {
#pragma unroll
        for (int j = 0; j < GTN; j += 4) {
            float4 v = make_float4(acc[i][j], acc[i][j+1], acc[i][j+2], acc[i][j+3]);
            *(float4*)&C[(size_t)(bm + tr + i) * N + bn + tc + j] = v;
        }
    }
}

// ---------------- RoPE (in-place) ----------------
// x: [ROWS][nheads*128]; position = row % SEQ
__global__ void rope_kernel(float* __restrict__ x, int nheads) {
    int idx = blockIdx.x * blockDim.x + threadIdx.x;
    int total = ROWS * nheads * 64;
    if (idx >= total) return;
    int d = idx & 63;
    int h = (idx >> 6) % nheads;
    int row = idx / (64 * nheads);
    int s = row & (SEQ - 1);
    float inv = 1.0f / powf(10000.0f, (2.0f * (float)d) / 128.0f);
    float ang = (float)s * inv;
    float sn, cs;
    sincosf(ang, &sn, &cs);
    size_t base = (size_t)row * ((size_t)nheads * HD) + (size_t)h * HD;
    float x1 = x[base + d];
    float x2 = x[base + d + 64];
    x[base + d]      = x1 * cs - x2 * sn;
    x[base + d + 64] = x2 * cs + x1 * sn;
}

// ---------------- Flash attention (fp32, causal, GQA) ----------------
// grid: (S/BQ=32, NH=32, BSZ=2), 256 threads
#define FBQ 64
#define FBC 64
#define SQ_STR 129
#define SK_STR 129
#define SV_STR 132
#define SP_STR 65
#define SQ_OFF 0
#define SK_OFF (FBQ * SQ_STR)                     // 8256
#define SV_OFF (SK_OFF + FBC * SK_STR)            // 16512
#define SP_OFF (SV_OFF + FBC * SV_STR)            // 24960
#define FSMEM_FLOATS (SP_OFF + FBQ * SP_STR)      // 29120
#define FSMEM_BYTES (FSMEM_FLOATS * 4)            // 116480

__global__ __launch_bounds__(256)
void flash_kernel(const float* __restrict__ Q, const float* __restrict__ K,
                  const float* __restrict__ V, float* __restrict__ O) {
    extern __shared__ float sm[];
    float* sQ = sm + SQ_OFF;
    float* sK = sm + SK_OFF;
    float* sV = sm + SV_OFF;
    float* sP = sm + SP_OFF;

    const int tid = threadIdx.x;
    const int qt = blockIdx.x;
    const int h  = blockIdx.y;
    const int b  = blockIdx.z;
    const int kvh = h >> 2;

    const float* Qp = Q + (size_t)b * SEQ * HID + (size_t)h * HD;
    const float* Kp = K + (size_t)b * SEQ * (NKV*HD) + (size_t)kvh * HD;
    const float* Vp = V + (size_t)b * SEQ * (NKV*HD) + (size_t)kvh * HD;
    float* Op = O + (size_t)b * SEQ * HID + (size_t)h * HD;

    const int q0 = qt * FBQ;
    const float qscale = 0.08838834764831845f;  // 1/sqrt(128)

    // Load + scale Q tile: 64x128 = 2048 float4
    for (int i = tid; i < FBQ * HD / 4; i += 256) {
        int r = i >> 5;
        int c4 = (i & 31) * 4;
        float4 v = *(const float4*)&Qp[(size_t)(q0 + r) * HID + c4];
        sQ[r * SQ_STR + c4 + 0] = v.x * qscale;
        sQ[r * SQ_STR + c4 + 1] = v.y * qscale;
        sQ[r * SQ_STR + c4 + 2] = v.z * qscale;
        sQ[r * SQ_STR + c4 + 3] = v.w * qscale;
    }

    const int rg = tid >> 4;   // row group: 4 rows
    const int cg = tid & 15;   // col group

    float m_i[4], l_i[4];
    float acc[4][8];
#pragma unroll
    for (int i = 0; i < 4; i++) {
        m_i[i] = -1e30f;
        l_i[i] = 0.0f;
#pragma unroll
        for (int d = 0; d < 8; d++) acc[i][d] = 0.0f;
    }

    const int ntiles = qt + 1;
    for (int j = 0; j < ntiles; j++) {
        __syncthreads();   // previous PV done before overwriting K/V
        // Load K/V tiles (64x128 each)
        for (int i = tid; i < FBC * HD / 4; i += 256) {
            int r = i >> 5;
            int c4 = (i & 31) * 4;
            float4 kv4 = *(const float4*)&Kp[(size_t)(j * FBC + r) * (NKV*HD) + c4];
            sK[r * SK_STR + c4 + 0] = kv4.x;
            sK[r * SK_STR + c4 + 1] = kv4.y;
            sK[r * SK_STR + c4 + 2] = kv4.z;
            sK[r * SK_STR + c4 + 3] = kv4.w;
            float4 vv4 = *(const float4*)&Vp[(size_t)(j * FBC + r) * (NKV*HD) + c4];
            *(float4*)&sV[r * SV_STR + c4] = vv4;
        }
        __syncthreads();

        // scores: s[4 rows][4 cols]
        float s[4][4];
#pragma unroll
        for (int i = 0; i < 4; i++)
#pragma unroll
            for (int j2 = 0; j2 < 4; j2++) s[i][j2] = 0.0f;

        for (int k = 0; k < HD; k++) {
            float qv[4], kv[4];
#pragma unroll
            for (int i = 0; i < 4; i++) qv[i] = sQ[(rg * 4 + i) * SQ_STR + k];
#pragma unroll
            for (int j2 = 0; j2 < 4; j2++) kv[j2] = sK[(cg * 4 + j2) * SK_STR + k];
#pragma unroll
            for (int i = 0; i < 4; i++)
#pragma unroll
                for (int j2 = 0; j2 < 4; j2++)
                    s[i][j2] = fmaf(qv[i], kv[j2], s[i][j2]);
        }

        // causal mask on diagonal tile
        if (j == qt) {
#pragma unroll
            for (int i = 0; i < 4; i++) {
                int qi = q0 + rg * 4 + i;
#pragma unroll
                for (int j2 = 0; j2 < 4; j2++) {
                    int ki = j * FBC + cg * 4 + j2;
                    if (ki > qi) s[i][j2] = -1e30f;
                }
            }
        }

        // online softmax update per row
#pragma unroll
        for (int i = 0; i < 4; i++) {
            float mx = fmaxf(fmaxf(s[i][0], s[i][1]), fmaxf(s[i][2], s[i][3]));
#pragma unroll
            for (int o = 8; o >= 1; o >>= 1)
                mx = fmaxf(mx, __shfl_xor_sync(0xffffffffu, mx, o));
            float mnew = fmaxf(m_i[i], mx);
            float scale = __expf(m_i[i] - mnew);
            float rsum = 0.0f;
#pragma unroll
            for (int j2 = 0; j2 < 4; j2++) {
                s[i][j2] = __expf(s[i][j2] - mnew);
                rsum += s[i][j2];
            }
#pragma unroll
            for (int o = 8; o >= 1; o >>= 1)
                rsum += __shfl_xor_sync(0xffffffffu, rsum, o);
            l_i[i] = l_i[i] * scale + rsum;
            m_i[i] = mnew;
#pragma unroll
            for (int d = 0; d < 8; d++) acc[i][d] *= scale;
#pragma unroll
            for (int j2 = 0; j2 < 4; j2++)
                sP[(rg * 4 + i) * SP_STR + cg * 4 + j2] = s[i][j2];
        }
        __syncthreads();

        // PV: O[4 rows][8 dims] += P @ V
        for (int c = 0; c < FBC; c++) {
            float4 v0 = *(const float4*)&sV[c * SV_STR + cg * 8];
            float4 v1 = *(const float4*)&sV[c * SV_STR + cg * 8 + 4];
#pragma unroll
            for (int i = 0; i < 4; i++) {
                float p = sP[(rg * 4 + i) * SP_STR + c];
                acc[i][0] = fmaf(p, v0.x, acc[i][0]);
                acc[i][1] = fmaf(p, v0.y, acc[i][1]);
                acc[i][2] = fmaf(p, v0.z, acc[i][2]);
                acc[i][3] = fmaf(p, v0.w, acc[i][3]);
                acc[i][4] = fmaf(p, v1.x, acc[i][4]);
                acc[i][5] = fmaf(p, v1.y, acc[i][5]);
                acc[i][6] = fmaf(p, v1.z, acc[i][6]);
                acc[i][7] = fmaf(p, v1.w, acc[i][7]);
            }
        }
    }

    // epilogue: normalize + store
#pragma unroll
    for (int i = 0; i < 4; i++) {
        float inv_l = 1.0f / l_i[i];
        int row = q0 + rg * 4 + i;
        float4 o0 = make_float4(acc[i][0]*inv_l, acc[i][1]*inv_l, acc[i][2]*inv_l, acc[i][3]*inv_l);
        float4 o1 = make_float4(acc[i][4]*inv_l, acc[i][5]*inv_l, acc[i][6]*inv_l, acc[i][7]*inv_l);
        *(float4*)&Op[(size_t)row * HID + cg * 8]     = o0;
        *(float4*)&Op[(size_t)row * HID + cg * 8 + 4] = o1;
    }
}

// ---------------- launch ----------------
extern "C" void kernel_launch(void* const* d_in, const int* in_sizes, int n_in,
                              void* d_out, int out_size) {
    (void)in_sizes; (void)n_in; (void)out_size;
    const float* X  = (const float*)d_in[0];
    // d_in[1] = attention_mask (causal, reimplemented), d_in[2] = position_ids (arange)
    const float* Wq = (const float*)d_in[3];
    const float* Wk = (const float*)d_in[4];
    const float* Wv = (const float*)d_in[5];
    const float* Wo = (const float*)d_in[6];
    float* out = (float*)d_out;

    float *Qb, *Kb, *Vb, *Ob;
    cudaGetSymbolAddress((void**)&Qb, g_Q);
    cudaGetSymbolAddress((void**)&Kb, g_K);
    cudaGetSymbolAddress((void**)&Vb, g_V);
    cudaGetSymbolAddress((void**)&Ob, g_O);

    cudaFuncSetAttribute(flash_kernel, cudaFuncAttributeMaxDynamicSharedMemorySize, FSMEM_BYTES);

    // QKV projections
    sgemm_kernel<<<dim3(HID / GBN, ROWS / GBM), 256>>>(X, Wq, Qb, ROWS, HID, HID);
    sgemm_kernel<<<dim3((NKV*HD) / GBN, ROWS / GBM), 256>>>(X, Wk, Kb, ROWS, NKV*HD, HID);
    sgemm_kernel<<<dim3((NKV*HD) / GBN, ROWS / GBM), 256>>>(X, Wv, Vb, ROWS, NKV*HD, HID);

    // RoPE on Q and K
    {
        int totq = ROWS * NH * 64;
        rope_kernel<<<(totq + 255) / 256, 256>>>(Qb, NH);
        int totk = ROWS * NKV * 64;
        rope_kernel<<<(totk + 255) / 256, 256>>>(Kb, NKV);
    }

    // Flash attention
    flash_kernel<<<dim3(SEQ / FBQ, NH, BSZ), 256, FSMEM_BYTES>>>(Qb, Kb, Vb, Ob);

    // Output projection
    sgemm_kernel<<<dim3(HID / GBN, ROWS / GBM), 256>>>(Ob, Wo, out, ROWS, HID, HID);
}

// round 3
// speedup vs baseline: 1.9722x; 1.9722x over previous
#include <cuda_runtime.h>
#include <cuda_bf16.h>
#include <math.h>
#include <stdint.h>

// Problem constants
#define BSZ 2
#define SEQ 2048
#define HID 4096
#define NH  32
#define NKV 8
#define HD  128
#define ROWS (BSZ*SEQ)           // 4096
#define KVD (NKV*HD)             // 1024

// ---------------- scratch (device globals; no allocation allowed) ----------------
__device__ float g_Q[(size_t)ROWS * HID];
__device__ float g_K[(size_t)ROWS * KVD];
__device__ float g_V[(size_t)ROWS * KVD];
__device__ float g_O[(size_t)ROWS * HID];
__device__ float g_Xt[(size_t)ROWS * HID];    // tf32-rounded X
__device__ float g_Ot[(size_t)ROWS * HID];    // tf32-rounded attn output
__device__ float g_Wqt[(size_t)HID * HID];
__device__ float g_Wkt[(size_t)HID * KVD];
__device__ float g_Wvt[(size_t)HID * KVD];
__device__ float g_Wot[(size_t)HID * HID];

__device__ __forceinline__ uint32_t smem_u32(const void* p) {
    uint32_t a;
    asm("{ .reg .u64 t; cvta.to.shared.u64 t, %1; cvt.u32.u64 %0, t; }" : "=r"(a) : "l"(p));
    return a;
}
__device__ __forceinline__ void cp16(uint32_t smem_addr, const void* gptr) {
    asm volatile("cp.async.cg.shared.global [%0], [%1], 16;" :: "r"(smem_addr), "l"(gptr) : "memory");
}
#define CP_COMMIT() asm volatile("cp.async.commit_group;" ::: "memory")
#define CP_WAIT0()  asm volatile("cp.async.wait_group 0;" ::: "memory")

// ---------------- tf32 rounding pre-pass ----------------
__global__ void cvt_tf32_kernel(const float4* __restrict__ in, float4* __restrict__ out, int n4) {
    int i = blockIdx.x * blockDim.x + threadIdx.x;
    if (i >= n4) return;
    float4 v = in[i];
    uint32_t x, y, z, w;
    asm("cvt.rna.tf32.f32 %0, %1;" : "=r"(x) : "f"(v.x));
    asm("cvt.rna.tf32.f32 %0, %1;" : "=r"(y) : "f"(v.y));
    asm("cvt.rna.tf32.f32 %0, %1;" : "=r"(z) : "f"(v.z));
    asm("cvt.rna.tf32.f32 %0, %1;" : "=r"(w) : "f"(v.w));
    out[i] = make_float4(__uint_as_float(x), __uint_as_float(y),
                         __uint_as_float(z), __uint_as_float(w));
}

// ================= tf32 mma.sync GEMM: C[M,N] = A[M,K] @ B[K,N] =================
// A, B already tf32-rounded fp32. BM=BN=128, BK=16, 256 threads (8 warps, 64x32 each).
#define ASTR 20     // floats per A smem row (conflict-free for fragment reads)
#define BSTR 136    // floats per B smem row

__global__ __launch_bounds__(256)
void tf32_mma_gemm(const float* __restrict__ A, const float* __restrict__ B,
                   float* __restrict__ C, int M, int N, int K) {
    __shared__ float As[2][128 * ASTR];
    __shared__ float Bs[2][16 * BSTR];

    const int tid = threadIdx.x;
    const int wid = tid >> 5;
    const int lid = tid & 31;
    const int gi = lid >> 2;   // 0..7
    const int qi = lid & 3;    // 0..3
    const int wm = (wid & 1) * 64;
    const int wn = (wid >> 1) * 32;

    const size_t bm = (size_t)blockIdx.y * 128;
    const size_t bn = (size_t)blockIdx.x * 128;
    const float* Ap = A + bm * K;
    const float* Bp = B + bn;

    const int aRow = tid >> 2;          // 0..63
    const int aCol = (tid & 3) * 4;     // 0,4,8,12
    const int bRow = tid >> 5;          // 0..7
    const int bCol = (tid & 31) * 4;    // 0..124

    float acc[4][4][4];
#pragma unroll
    for (int mt = 0; mt < 4; mt++)
#pragma unroll
        for (int nt = 0; nt < 4; nt++)
#pragma unroll
            for (int r = 0; r < 4; r++) acc[mt][nt][r] = 0.0f;

    // prefetch stage 0
    {
        uint32_t as = smem_u32(&As[0][0]);
        uint32_t bs = smem_u32(&Bs[0][0]);
#pragma unroll
        for (int r = 0; r < 2; r++) {
            int row = aRow + r * 64;
            cp16(as + (row * ASTR + aCol) * 4, Ap + (size_t)row * K + aCol);
        }
#pragma unroll
        for (int r = 0; r < 2; r++) {
            int row = bRow + r * 8;
            cp16(bs + (row * BSTR + bCol) * 4, Bp + (size_t)row * N + bCol);
        }
        CP_COMMIT();
    }

    const int nsteps = K / 16;
    for (int step = 0; step < nsteps; step++) {
        const int cur = step & 1;
        CP_WAIT0();
        __syncthreads();

        if (step + 1 < nsteps) {
            const int nxt = (step + 1) & 1;
            const int k0 = (step + 1) * 16;
            uint32_t as = smem_u32(&As[nxt][0]);
            uint32_t bs = smem_u32(&Bs[nxt][0]);
#pragma unroll
            for (int r = 0; r < 2; r++) {
                int row = aRow + r * 64;
                cp16(as + (row * ASTR + aCol) * 4, Ap + (size_t)row * K + k0 + aCol);
            }
#pragma unroll
            for (int r = 0; r < 2; r++) {
                int row = bRow + r * 8;
                cp16(bs + (row * BSTR + bCol) * 4, Bp + (size_t)(k0 + row) * N + bCol);
            }
            CP_COMMIT();
        }

        const float* Ab = &As[cur][0];
        const float* Bb = &Bs[cur][0];
#pragma unroll
        for (int kk = 0; kk < 16; kk += 8) {
            uint32_t a[4][4], b[4][2];
#pragma unroll
            for (int mt = 0; mt < 4; mt++) {
                int r = wm + mt * 16 + gi;
                a[mt][0] = __float_as_uint(Ab[r * ASTR + kk + qi]);
                a[mt][1] = __float_as_uint(Ab[(r + 8) * ASTR + kk + qi]);
                a[mt][2] = __float_as_uint(Ab[r * ASTR + kk + qi + 4]);
                a[mt][3] = __float_as_uint(Ab[(r + 8) * ASTR + kk + qi + 4]);
            }
#pragma unroll
            for (int nt = 0; nt < 4; nt++) {
                int c = wn + nt * 8 + gi;
                b[nt][0] = __float_as_uint(Bb[(kk + qi) * BSTR + c]);
                b[nt][1] = __float_as_uint(Bb[(kk + qi + 4) * BSTR + c]);
            }
#pragma unroll
            for (int mt = 0; mt < 4; mt++)
#pragma unroll
                for (int nt = 0; nt < 4; nt++) {
                    asm volatile(
                        "mma.sync.aligned.m16n8k8.row.col.f32.tf32.tf32.f32 "
                        "{%0,%1,%2,%3}, {%4,%5,%6,%7}, {%8,%9}, {%0,%1,%2,%3};"
                        : "+f"(acc[mt][nt][0]), "+f"(acc[mt][nt][1]),
                          "+f"(acc[mt][nt][2]), "+f"(acc[mt][nt][3])
                        : "r"(a[mt][0]), "r"(a[mt][1]), "r"(a[mt][2]), "r"(a[mt][3]),
                          "r"(b[nt][0]), "r"(b[nt][1]));
                }
        }
        __syncthreads();
    }

    // epilogue
#pragma unroll
    for (int mt = 0; mt < 4; mt++) {
#pragma unroll
        for (int nt = 0; nt < 4; nt++) {
            size_t row = bm + wm + mt * 16 + gi;
            size_t col = bn + wn + nt * 8 + qi * 2;
            *(float2*)&C[row * N + col] = make_float2(acc[mt][nt][0], acc[mt][nt][1]);
            *(float2*)&C[(row + 8) * N + col] = make_float2(acc[mt][nt][2], acc[mt][nt][3]);
        }
    }
}

// ---------------- RoPE (in-place) ----------------
__global__ void rope_kernel(float* __restrict__ x, int nheads) {
    int idx = blockIdx.x * blockDim.x + threadIdx.x;
    int total = ROWS * nheads * 64;
    if (idx >= total) return;
    int d = idx & 63;
    int h = (idx >> 6) % nheads;
    int row = idx / (64 * nheads);
    int s = row & (SEQ - 1);
    float inv = 1.0f / powf(10000.0f, (2.0f * (float)d) / 128.0f);
    float ang = (float)s * inv;
    float sn, cs;
    sincosf(ang, &sn, &cs);
    size_t base = (size_t)row * ((size_t)nheads * HD) + (size_t)h * HD;
    float x1 = x[base + d];
    float x2 = x[base + d + 64];
    x[base + d]      = x1 * cs - x2 * sn;
    x[base + d + 64] = x2 * cs + x1 * sn;
}

// ---------------- Flash attention (fp32, causal, GQA) ----------------
#define FBQ 64
#define FBC 64
#define SQ_STR 129
#define SK_STR 129
#define SV_STR 132
#define SP_STR 65
#define SQ_OFF 0
#define SK_OFF (FBQ * SQ_STR)
#define SV_OFF (SK_OFF + FBC * SK_STR)
#define SP_OFF (SV_OFF + FBC * SV_STR)
#define FSMEM_FLOATS (SP_OFF + FBQ * SP_STR)
#define FSMEM_BYTES (FSMEM_FLOATS * 4)

__global__ __launch_bounds__(256)
void flash_kernel(const float* __restrict__ Q, const float* __restrict__ K,
                  const float* __restrict__ V, float* __restrict__ O) {
    extern __shared__ float sm[];
    float* sQ = sm + SQ_OFF;
    float* sK = sm + SK_OFF;
    float* sV = sm + SV_OFF;
    float* sP = sm + SP_OFF;

    const int tid = threadIdx.x;
    const int qt = blockIdx.x;
    const int h  = blockIdx.y;
    const int b  = blockIdx.z;
    const int kvh = h >> 2;

    const float* Qp = Q + (size_t)b * SEQ * HID + (size_t)h * HD;
    const float* Kp = K + (size_t)b * SEQ * KVD + (size_t)kvh * HD;
    const float* Vp = V + (size_t)b * SEQ * KVD + (size_t)kvh * HD;
    float* Op = O + (size_t)b * SEQ * HID + (size_t)h * HD;

    const int q0 = qt * FBQ;
    const float qscale = 0.08838834764831845f;

    for (int i = tid; i < FBQ * HD / 4; i += 256) {
        int r = i >> 5;
        int c4 = (i & 31) * 4;
        float4 v = *(const float4*)&Qp[(size_t)(q0 + r) * HID + c4];
        sQ[r * SQ_STR + c4 + 0] = v.x * qscale;
        sQ[r * SQ_STR + c4 + 1] = v.y * qscale;
        sQ[r * SQ_STR + c4 + 2] = v.z * qscale;
        sQ[r * SQ_STR + c4 + 3] = v.w * qscale;
    }

    const int rg = tid >> 4;
    const int cg = tid & 15;

    float m_i[4], l_i[4];
    float acc[4][8];
#pragma unroll
    for (int i = 0; i < 4; i++) {
        m_i[i] = -1e30f;
        l_i[i] = 0.0f;
#pragma unroll
        for (int d = 0; d < 8; d++) acc[i][d] = 0.0f;
    }

    const int ntiles = qt + 1;
    for (int j = 0; j < ntiles; j++) {
        __syncthreads();
        for (int i = tid; i < FBC * HD / 4; i += 256) {
            int r = i >> 5;
            int c4 = (i & 31) * 4;
            float4 kv4 = *(const float4*)&Kp[(size_t)(j * FBC + r) * KVD + c4];
            sK[r * SK_STR + c4 + 0] = kv4.x;
            sK[r * SK_STR + c4 + 1] = kv4.y;
            sK[r * SK_STR + c4 + 2] = kv4.z;
            sK[r * SK_STR + c4 + 3] = kv4.w;
            float4 vv4 = *(const float4*)&Vp[(size_t)(j * FBC + r) * KVD + c4];
            *(float4*)&sV[r * SV_STR + c4] = vv4;
        }
        __syncthreads();

        float s[4][4];
#pragma unroll
        for (int i = 0; i < 4; i++)
#pragma unroll
            for (int j2 = 0; j2 < 4; j2++) s[i][j2] = 0.0f;

        for (int k = 0; k < HD; k++) {
            float qv[4], kv[4];
#pragma unroll
            for (int i = 0; i < 4; i++) qv[i] = sQ[(rg * 4 + i) * SQ_STR + k];
#pragma unroll
            for (int j2 = 0; j2 < 4; j2++) kv[j2] = sK[(cg * 4 + j2) * SK_STR + k];
#pragma unroll
            for (int i = 0; i < 4; i++)
#pragma unroll
                for (int j2 = 0; j2 < 4; j2++)
                    s[i][j2] = fmaf(qv[i], kv[j2], s[i][j2]);
        }

        if (j == qt) {
#pragma unroll
            for (int i = 0; i < 4; i++) {
                int qi2 = q0 + rg * 4 + i;
#pragma unroll
                for (int j2 = 0; j2 < 4; j2++) {
                    int ki = j * FBC + cg * 4 + j2;
                    if (ki > qi2) s[i][j2] = -1e30f;
                }
            }
        }

#pragma unroll
        for (int i = 0; i < 4; i++) {
            float mx = fmaxf(fmaxf(s[i][0], s[i][1]), fmaxf(s[i][2], s[i][3]));
#pragma unroll
            for (int o = 8; o >= 1; o >>= 1)
                mx = fmaxf(mx, __shfl_xor_sync(0xffffffffu, mx, o));
            float mnew = fmaxf(m_i[i], mx);
            float scale = __expf(m_i[i] - mnew);
            float rsum = 0.0f;
#pragma unroll
            for (int j2 = 0; j2 < 4; j2++) {
                s[i][j2] = __expf(s[i][j2] - mnew);
                rsum += s[i][j2];
            }
#pragma unroll
            for (int o = 8; o >= 1; o >>= 1)
                rsum += __shfl_xor_sync(0xffffffffu, rsum, o);
            l_i[i] = l_i[i] * scale + rsum;
            m_i[i] = mnew;
#pragma unroll
            for (int d = 0; d < 8; d++) acc[i][d] *= scale;
#pragma unroll
            for (int j2 = 0; j2 < 4; j2++)
                sP[(rg * 4 + i) * SP_STR + cg * 4 + j2] = s[i][j2];
        }
        __syncthreads();

        for (int c = 0; c < FBC; c++) {
            float4 v0 = *(const float4*)&sV[c * SV_STR + cg * 8];
            float4 v1 = *(const float4*)&sV[c * SV_STR + cg * 8 + 4];
#pragma unroll
            for (int i = 0; i < 4; i++) {
                float p = sP[(rg * 4 + i) * SP_STR + c];
                acc[i][0] = fmaf(p, v0.x, acc[i][0]);
                acc[i][1] = fmaf(p, v0.y, acc[i][1]);
                acc[i][2] = fmaf(p, v0.z, acc[i][2]);
                acc[i][3] = fmaf(p, v0.w, acc[i][3]);
                acc[i][4] = fmaf(p, v1.x, acc[i][4]);
                acc[i][5] = fmaf(p, v1.y, acc[i][5]);
                acc[i][6] = fmaf(p, v1.z, acc[i][6]);
                acc[i][7] = fmaf(p, v1.w, acc[i][7]);
            }
        }
    }

#pragma unroll
    for (int i = 0; i < 4; i++) {
        float inv_l = 1.0f / l_i[i];
        int row = q0 + rg * 4 + i;
        float4 o0 = make_float4(acc[i][0]*inv_l, acc[i][1]*inv_l, acc[i][2]*inv_l, acc[i][3]*inv_l);
        float4 o1 = make_float4(acc[i][4]*inv_l, acc[i][5]*inv_l, acc[i][6]*inv_l, acc[i][7]*inv_l);
        *(float4*)&Op[(size_t)row * HID + cg * 8]     = o0;
        *(float4*)&Op[(size_t)row * HID + cg * 8 + 4] = o1;
    }
}

// ---------------- launch ----------------
extern "C" void kernel_launch(void* const* d_in, const int* in_sizes, int n_in,
                              void* d_out, int out_size) {
    (void)in_sizes; (void)n_in; (void)out_size;
    const float* X  = (const float*)d_in[0];
    const float* Wq = (const float*)d_in[3];
    const float* Wk = (const float*)d_in[4];
    const float* Wv = (const float*)d_in[5];
    const float* Wo = (const float*)d_in[6];
    float* out = (float*)d_out;

    float *Qb, *Kb, *Vb, *Ob, *Xt, *Ot, *Wqt, *Wkt, *Wvt, *Wot;
    cudaGetSymbolAddress((void**)&Qb, g_Q);
    cudaGetSymbolAddress((void**)&Kb, g_K);
    cudaGetSymbolAddress((void**)&Vb, g_V);
    cudaGetSymbolAddress((void**)&Ob, g_O);
    cudaGetSymbolAddress((void**)&Xt, g_Xt);
    cudaGetSymbolAddress((void**)&Ot, g_Ot);
    cudaGetSymbolAddress((void**)&Wqt, g_Wqt);
    cudaGetSymbolAddress((void**)&Wkt, g_Wkt);
    cudaGetSymbolAddress((void**)&Wvt, g_Wvt);
    cudaGetSymbolAddress((void**)&Wot, g_Wot);

    cudaFuncSetAttribute(flash_kernel, cudaFuncAttributeMaxDynamicSharedMemorySize, FSMEM_BYTES);

    // tf32 rounding pre-pass
    {
        int n4;
        n4 = ROWS * HID / 4;
        cvt_tf32_kernel<<<(n4 + 255) / 256, 256>>>((const float4*)X, (float4*)Xt, n4);
        n4 = HID * HID / 4;
        cvt_tf32_kernel<<<(n4 + 255) / 256, 256>>>((const float4*)Wq, (float4*)Wqt, n4);
        n4 = HID * KVD / 4;
        cvt_tf32_kernel<<<(n4 + 255) / 256, 256>>>((const float4*)Wk, (float4*)Wkt, n4);
        cvt_tf32_kernel<<<(n4 + 255) / 256, 256>>>((const float4*)Wv, (float4*)Wvt, n4);
        n4 = HID * HID / 4;
        cvt_tf32_kernel<<<(n4 + 255) / 256, 256>>>((const float4*)Wo, (float4*)Wot, n4);
    }

    // QKV projections (tensor-core tf32)
    tf32_mma_gemm<<<dim3(HID / 128, ROWS / 128), 256>>>(Xt, Wqt, Qb, ROWS, HID, HID);
    tf32_mma_gemm<<<dim3(KVD / 128, ROWS / 128), 256>>>(Xt, Wkt, Kb, ROWS, KVD, HID);
    tf32_mma_gemm<<<dim3(KVD / 128, ROWS / 128), 256>>>(Xt, Wvt, Vb, ROWS, KVD, HID);

    // RoPE
    {
        int totq = ROWS * NH * 64;
        rope_kernel<<<(totq + 255) / 256, 256>>>(Qb, NH);
        int totk = ROWS * NKV * 64;
        rope_kernel<<<(totk + 255) / 256, 256>>>(Kb, NKV);
    }

    // Flash attention
    flash_kernel<<<dim3(SEQ / FBQ, NH, BSZ), 256, FSMEM_BYTES>>>(Qb, Kb, Vb, Ob);

    // Output projection
    {
        int n4 = ROWS * HID / 4;
        cvt_tf32_kernel<<<(n4 + 255) / 256, 256>>>((const float4*)Ob, (float4*)Ot, n4);
    }
    tf32_mma_gemm<<<dim3(HID / 128, ROWS / 128), 256>>>(Ot, Wot, out, ROWS, HID, HID);
}

// round 4
// speedup vs baseline: 4.0066x; 2.0315x over previous
#include <cuda_runtime.h>
#include <cuda_bf16.h>
#include <math.h>
#include <stdint.h>

// Problem constants
#define BSZ 2
#define SEQ 2048
#define HID 4096
#define NH  32
#define NKV 8
#define HD  128
#define ROWS (BSZ*SEQ)           // 4096
#define KVD (NKV*HD)             // 1024

// ---------------- scratch ----------------
__device__ float g_Q[(size_t)ROWS * HID];
__device__ float g_K[(size_t)ROWS * KVD];
__device__ float g_V[(size_t)ROWS * KVD];
__device__ float g_O[(size_t)ROWS * HID];
__device__ float g_Xt[(size_t)ROWS * HID];
__device__ float g_Ot[(size_t)ROWS * HID];
__device__ float g_Wqt[(size_t)HID * HID];
__device__ float g_Wkt[(size_t)HID * KVD];
__device__ float g_Wvt[(size_t)HID * KVD];
__device__ float g_Wot[(size_t)HID * HID];

__device__ __forceinline__ uint32_t smem_u32(const void* p) {
    uint32_t a;
    asm("{ .reg .u64 t; cvta.to.shared.u64 t, %1; cvt.u32.u64 %0, t; }" : "=r"(a) : "l"(p));
    return a;
}
__device__ __forceinline__ void cp16(uint32_t smem_addr, const void* gptr) {
    asm volatile("cp.async.cg.shared.global [%0], [%1], 16;" :: "r"(smem_addr), "l"(gptr) : "memory");
}
#define CP_COMMIT() asm volatile("cp.async.commit_group;" ::: "memory")
#define CP_WAIT0()  asm volatile("cp.async.wait_group 0;" ::: "memory")

__device__ __forceinline__ uint32_t f2tf32(float f) {
    uint32_t u;
    asm("cvt.rna.tf32.f32 %0, %1;" : "=r"(u) : "f"(f));
    return u;
}
__device__ __forceinline__ void mma_tf32(float* c, uint32_t a0, uint32_t a1, uint32_t a2,
                                         uint32_t a3, uint32_t b0, uint32_t b1) {
    asm volatile(
        "mma.sync.aligned.m16n8k8.row.col.f32.tf32.tf32.f32 "
        "{%0,%1,%2,%3}, {%4,%5,%6,%7}, {%8,%9}, {%0,%1,%2,%3};"
        : "+f"(c[0]), "+f"(c[1]), "+f"(c[2]), "+f"(c[3])
        : "r"(a0), "r"(a1), "r"(a2), "r"(a3), "r"(b0), "r"(b1));
}

// ---------------- tf32 rounding pre-pass ----------------
__global__ void cvt_tf32_kernel(const float4* __restrict__ in, float4* __restrict__ out, int n4) {
    int i = blockIdx.x * blockDim.x + threadIdx.x;
    if (i >= n4) return;
    float4 v = in[i];
    out[i] = make_float4(__uint_as_float(f2tf32(v.x)), __uint_as_float(f2tf32(v.y)),
                         __uint_as_float(f2tf32(v.z)), __uint_as_float(f2tf32(v.w)));
}

// ================= tf32 mma GEMM: C[M,N] = A[M,K] @ B[K,N] =================
// 128x128 block, 128 threads (4 warps x 64x64), BK=16, 2-stage cp.async.
#define ASTR 20
#define BSTR 136

__global__ __launch_bounds__(128)
void tf32_mma_gemm(const float* __restrict__ A, const float* __restrict__ B,
                   float* __restrict__ C, int M, int N, int K) {
    __shared__ float As[2][128 * ASTR];
    __shared__ float Bs[2][16 * BSTR];

    const int tid = threadIdx.x;
    const int wid = tid >> 5;
    const int lid = tid & 31;
    const int gi = lid >> 2;
    const int qi = lid & 3;
    const int wm = (wid & 1) * 64;
    const int wn = (wid >> 1) * 64;

    const size_t bm = (size_t)blockIdx.y * 128;
    const size_t bn = (size_t)blockIdx.x * 128;
    const float* Ap = A + bm * K;
    const float* Bp = B + bn;

    float acc[4][8][4];
#pragma unroll
    for (int mt = 0; mt < 4; mt++)
#pragma unroll
        for (int nt = 0; nt < 8; nt++)
#pragma unroll
            for (int r = 0; r < 4; r++) acc[mt][nt][r] = 0.0f;

    // prefetch stage 0
    {
        uint32_t as = smem_u32(&As[0][0]);
        uint32_t bs = smem_u32(&Bs[0][0]);
#pragma unroll
        for (int r = 0; r < 4; r++) {
            int i = tid + r * 128;
            int row = i >> 2, c4 = (i & 3) * 4;
            cp16(as + (row * ASTR + c4) * 4, Ap + (size_t)row * K + c4);
        }
#pragma unroll
        for (int r = 0; r < 4; r++) {
            int i = tid + r * 128;
            int row = i >> 5, c4 = (i & 31) * 4;
            cp16(bs + (row * BSTR + c4) * 4, Bp + (size_t)row * N + c4);
        }
        CP_COMMIT();
    }

    const int nsteps = K / 16;
    for (int step = 0; step < nsteps; step++) {
        const int cur = step & 1;
        CP_WAIT0();
        __syncthreads();

        if (step + 1 < nsteps) {
            const int nxt = (step + 1) & 1;
            const int k0 = (step + 1) * 16;
            uint32_t as = smem_u32(&As[nxt][0]);
            uint32_t bs = smem_u32(&Bs[nxt][0]);
#pragma unroll
            for (int r = 0; r < 4; r++) {
                int i = tid + r * 128;
                int row = i >> 2, c4 = (i & 3) * 4;
                cp16(as + (row * ASTR + c4) * 4, Ap + (size_t)row * K + k0 + c4);
            }
#pragma unroll
            for (int r = 0; r < 4; r++) {
                int i = tid + r * 128;
                int row = i >> 5, c4 = (i & 31) * 4;
                cp16(bs + (row * BSTR + c4) * 4, Bp + (size_t)(k0 + row) * N + c4);
            }
            CP_COMMIT();
        }

        const float* Ab = &As[cur][0];
        const float* Bb = &Bs[cur][0];
#pragma unroll
        for (int kk = 0; kk < 16; kk += 8) {
            uint32_t a[4][4], b[8][2];
#pragma unroll
            for (int mt = 0; mt < 4; mt++) {
                int r = wm + mt * 16 + gi;
                a[mt][0] = __float_as_uint(Ab[r * ASTR + kk + qi]);
                a[mt][1] = __float_as_uint(Ab[(r + 8) * ASTR + kk + qi]);
                a[mt][2] = __float_as_uint(Ab[r * ASTR + kk + qi + 4]);
                a[mt][3] = __float_as_uint(Ab[(r + 8) * ASTR + kk + qi + 4]);
            }
#pragma unroll
            for (int nt = 0; nt < 8; nt++) {
                int c = wn + nt * 8 + gi;
                b[nt][0] = __float_as_uint(Bb[(kk + qi) * BSTR + c]);
                b[nt][1] = __float_as_uint(Bb[(kk + qi + 4) * BSTR + c]);
            }
#pragma unroll
            for (int mt = 0; mt < 4; mt++)
#pragma unroll
                for (int nt = 0; nt < 8; nt++)
                    mma_tf32(acc[mt][nt], a[mt][0], a[mt][1], a[mt][2], a[mt][3],
                             b[nt][0], b[nt][1]);
        }
        __syncthreads();
    }

#pragma unroll
    for (int mt = 0; mt < 4; mt++) {
#pragma unroll
        for (int nt = 0; nt < 8; nt++) {
            size_t row = bm + wm + mt * 16 + gi;
            size_t col = bn + wn + nt * 8 + qi * 2;
            *(float2*)&C[row * N + col] = make_float2(acc[mt][nt][0], acc[mt][nt][1]);
            *(float2*)&C[(row + 8) * N + col] = make_float2(acc[mt][nt][2], acc[mt][nt][3]);
        }
    }
}

// ---------------- RoPE (in-place, rounds output to tf32) ----------------
__global__ void rope_kernel(float* __restrict__ x, int nheads) {
    int idx = blockIdx.x * blockDim.x + threadIdx.x;
    int total = ROWS * nheads * 64;
    if (idx >= total) return;
    int d = idx & 63;
    int h = (idx >> 6) % nheads;
    int row = idx / (64 * nheads);
    int s = row & (SEQ - 1);
    float inv = 1.0f / powf(10000.0f, (2.0f * (float)d) / 128.0f);
    float ang = (float)s * inv;
    float sn, cs;
    sincosf(ang, &sn, &cs);
    size_t base = (size_t)row * ((size_t)nheads * HD) + (size_t)h * HD;
    float x1 = x[base + d];
    float x2 = x[base + d + 64];
    x[base + d]      = __uint_as_float(f2tf32(x1 * cs - x2 * sn));
    x[base + d + 64] = __uint_as_float(f2tf32(x2 * cs + x1 * sn));
}

// ================= Flash attention (tf32 mma, causal, GQA) =================
// BQ=128, BC=64, 256 threads (8 warps, each owns 16 q-rows).
#define QSTR 132
#define KSTR 132
#define VSTR 136
#define SQ_OFF 0
#define SK0_OFF (128 * QSTR)                 // 16896
#define SK1_OFF (SK0_OFF + 64 * KSTR)        // 25344
#define SV0_OFF (SK1_OFF + 64 * KSTR)        // 33792
#define SV1_OFF (SV0_OFF + 64 * VSTR)        // 42496
#define FSM_FLOATS (SV1_OFF + 64 * VSTR)     // 51200
#define FSM_BYTES (FSM_FLOATS * 4)           // 204800

__global__ __launch_bounds__(256)
void flash_mma_kernel(const float* __restrict__ Q, const float* __restrict__ K,
                      const float* __restrict__ V, float* __restrict__ O) {
    extern __shared__ float sm[];
    const int tid = threadIdx.x;
    const int wid = tid >> 5;
    const int lid = tid & 31;
    const int gi = lid >> 2;
    const int qi = lid & 3;
    const int wm = wid * 16;

    const int qt = blockIdx.x;
    const int h  = blockIdx.y;
    const int b  = blockIdx.z;
    const int kvh = h >> 2;
    const int q0 = qt * 128;

    const float* Qp = Q + (size_t)b * SEQ * HID + (size_t)h * HD;
    const float* Kp = K + (size_t)b * SEQ * KVD + (size_t)kvh * HD;
    const float* Vp = V + (size_t)b * SEQ * KVD + (size_t)kvh * HD;
    float* Op = O + (size_t)b * SEQ * HID + (size_t)h * HD;

    const uint32_t smb = smem_u32(sm);

    // load Q tile (pre-rounded tf32-in-fp32)
    for (int i = tid; i < 128 * 32; i += 256) {
        int row = i >> 5, c4 = (i & 31) * 4;
        *(float4*)&sm[SQ_OFF + row * QSTR + c4] =
            *(const float4*)&Qp[(size_t)(q0 + row) * HID + c4];
    }

    float m0 = -1e30f, m1 = -1e30f, l0 = 0.0f, l1 = 0.0f;
    float o[16][4];
#pragma unroll
    for (int f = 0; f < 16; f++)
#pragma unroll
        for (int r = 0; r < 4; r++) o[f][r] = 0.0f;

    const int ntiles = 2 * qt + 2;
    const float qscale = 0.08838834764831845f;

    // prefetch tile 0
    {
        uint32_t kb = smb + SK0_OFF * 4;
        uint32_t vb = smb + SV0_OFF * 4;
        for (int i = tid; i < 64 * 32; i += 256) {
            int row = i >> 5, c4 = (i & 31) * 4;
            cp16(kb + (row * KSTR + c4) * 4, Kp + (size_t)row * KVD + c4);
            cp16(vb + (row * VSTR + c4) * 4, Vp + (size_t)row * KVD + c4);
        }
        CP_COMMIT();
    }

    for (int j = 0; j < ntiles; j++) {
        const int cur = j & 1;
        CP_WAIT0();
        __syncthreads();

        if (j + 1 < ntiles) {
            const int nxt = (j + 1) & 1;
            uint32_t kb = smb + (nxt ? SK1_OFF : SK0_OFF) * 4;
            uint32_t vb = smb + (nxt ? SV1_OFF : SV0_OFF) * 4;
            const size_t r0 = (size_t)(j + 1) * 64;
            for (int i = tid; i < 64 * 32; i += 256) {
                int row = i >> 5, c4 = (i & 31) * 4;
                cp16(kb + (row * KSTR + c4) * 4, Kp + (r0 + row) * KVD + c4);
                cp16(vb + (row * VSTR + c4) * 4, Vp + (r0 + row) * KVD + c4);
            }
            CP_COMMIT();
        }

        const float* sK = sm + (cur ? SK1_OFF : SK0_OFF);
        const float* sV = sm + (cur ? SV1_OFF : SV0_OFF);
        const float* sQ = sm + SQ_OFF;

        // ---- QK^T: S[16][64] per warp ----
        float s[8][4];
#pragma unroll
        for (int nt = 0; nt < 8; nt++)
#pragma unroll
            for (int r = 0; r < 4; r++) s[nt][r] = 0.0f;

#pragma unroll
        for (int kk = 0; kk < 128; kk += 8) {
            uint32_t a0 = __float_as_uint(sQ[(wm + gi) * QSTR + kk + qi]);
            uint32_t a1 = __float_as_uint(sQ[(wm + gi + 8) * QSTR + kk + qi]);
            uint32_t a2 = __float_as_uint(sQ[(wm + gi) * QSTR + kk + qi + 4]);
            uint32_t a3 = __float_as_uint(sQ[(wm + gi + 8) * QSTR + kk + qi + 4]);
#pragma unroll
            for (int nt = 0; nt < 8; nt++) {
                uint32_t b0 = __float_as_uint(sK[(nt * 8 + gi) * KSTR + kk + qi]);
                uint32_t b1 = __float_as_uint(sK[(nt * 8 + gi) * KSTR + kk + qi + 4]);
                mma_tf32(s[nt], a0, a1, a2, a3, b0, b1);
            }
        }

        // ---- softmax (rows wm+gi, wm+gi+8) ----
        const int row0 = q0 + wm + gi;
        const int row1 = row0 + 8;
        const bool diag = (j >= 2 * qt);
#pragma unroll
        for (int nt = 0; nt < 8; nt++) {
#pragma unroll
            for (int r = 0; r < 4; r++) s[nt][r] *= qscale;
            if (diag) {
                int c = j * 64 + nt * 8 + 2 * qi;
                if (c > row0)     s[nt][0] = -1e30f;
                if (c + 1 > row0) s[nt][1] = -1e30f;
                if (c > row1)     s[nt][2] = -1e30f;
                if (c + 1 > row1) s[nt][3] = -1e30f;
            }
        }
        float mx0 = -1e30f, mx1 = -1e30f;
#pragma unroll
        for (int nt = 0; nt < 8; nt++) {
            mx0 = fmaxf(mx0, fmaxf(s[nt][0], s[nt][1]));
            mx1 = fmaxf(mx1, fmaxf(s[nt][2], s[nt][3]));
        }
        mx0 = fmaxf(mx0, __shfl_xor_sync(0xffffffffu, mx0, 1));
        mx0 = fmaxf(mx0, __shfl_xor_sync(0xffffffffu, mx0, 2));
        mx1 = fmaxf(mx1, __shfl_xor_sync(0xffffffffu, mx1, 1));
        mx1 = fmaxf(mx1, __shfl_xor_sync(0xffffffffu, mx1, 2));

        float mn0 = fmaxf(m0, mx0), mn1 = fmaxf(m1, mx1);
        float sc0 = __expf(m0 - mn0), sc1 = __expf(m1 - mn1);
        m0 = mn0; m1 = mn1;

        float rs0 = 0.0f, rs1 = 0.0f;
        uint32_t pu[8][4];
#pragma unroll
        for (int nt = 0; nt < 8; nt++) {
            float p0 = __expf(s[nt][0] - m0);
            float p1 = __expf(s[nt][1] - m0);
            float p2 = __expf(s[nt][2] - m1);
            float p3 = __expf(s[nt][3] - m1);
            rs0 += p0 + p1;
            rs1 += p2 + p3;
            pu[nt][0] = f2tf32(p0);
            pu[nt][1] = f2tf32(p1);
            pu[nt][2] = f2tf32(p2);
            pu[nt][3] = f2tf32(p3);
        }
        rs0 += __shfl_xor_sync(0xffffffffu, rs0, 1);
        rs0 += __shfl_xor_sync(0xffffffffu, rs0, 2);
        rs1 += __shfl_xor_sync(0xffffffffu, rs1, 1);
        rs1 += __shfl_xor_sync(0xffffffffu, rs1, 2);
        l0 = l0 * sc0 + rs0;
        l1 = l1 * sc1 + rs1;
#pragma unroll
        for (int f = 0; f < 16; f++) {
            o[f][0] *= sc0; o[f][1] *= sc0;
            o[f][2] *= sc1; o[f][3] *= sc1;
        }

        // ---- PV: transpose P frags via shfl, then mma ----
        const int srcA = (gi << 2) + (qi >> 1);
        const int srcB = srcA + 2;
        const bool odd = (qi & 1);
#pragma unroll
        for (int kc = 0; kc < 8; kc++) {
            uint32_t x0 = __shfl_sync(0xffffffffu, pu[kc][0], srcA);
            uint32_t x1 = __shfl_sync(0xffffffffu, pu[kc][1], srcA);
            uint32_t y0 = __shfl_sync(0xffffffffu, pu[kc][0], srcB);
            uint32_t y1 = __shfl_sync(0xffffffffu, pu[kc][1], srcB);
            uint32_t x2 = __shfl_sync(0xffffffffu, pu[kc][2], srcA);
            uint32_t x3 = __shfl_sync(0xffffffffu, pu[kc][3], srcA);
            uint32_t y2 = __shfl_sync(0xffffffffu, pu[kc][2], srcB);
            uint32_t y3 = __shfl_sync(0xffffffffu, pu[kc][3], srcB);
            uint32_t a0 = odd ? x1 : x0;
            uint32_t a2 = odd ? y1 : y0;
            uint32_t a1 = odd ? x3 : x2;
            uint32_t a3 = odd ? y3 : y2;
#pragma unroll
            for (int nt2 = 0; nt2 < 16; nt2++) {
                uint32_t b0 = __float_as_uint(sV[(kc * 8 + qi) * VSTR + nt2 * 8 + gi]);
                uint32_t b1 = __float_as_uint(sV[(kc * 8 + qi + 4) * VSTR + nt2 * 8 + gi]);
                mma_tf32(o[nt2], a0, a1, a2, a3, b0, b1);
            }
        }
    }

    // epilogue
    const float inv0 = 1.0f / l0;
    const float inv1 = 1.0f / l1;
    const size_t r0 = (size_t)(q0 + wm + gi);
    const size_t r1 = r0 + 8;
#pragma unroll
    for (int nt2 = 0; nt2 < 16; nt2++) {
        int col = nt2 * 8 + 2 * qi;
        *(float2*)&Op[r0 * HID + col] = make_float2(o[nt2][0] * inv0, o[nt2][1] * inv0);
        *(float2*)&Op[r1 * HID + col] = make_float2(o[nt2][2] * inv1, o[nt2][3] * inv1);
    }
}

// ---------------- launch ----------------
extern "C" void kernel_launch(void* const* d_in, const int* in_sizes, int n_in,
                              void* d_out, int out_size) {
    (void)in_sizes; (void)n_in; (void)out_size;
    const float* X  = (const float*)d_in[0];
    const float* Wq = (const float*)d_in[3];
    const float* Wk = (const float*)d_in[4];
    const float* Wv = (const float*)d_in[5];
    const float* Wo = (const float*)d_in[6];
    float* out = (float*)d_out;

    float *Qb, *Kb, *Vb, *Ob, *Xt, *Ot, *Wqt, *Wkt, *Wvt, *Wot;
    cudaGetSymbolAddress((void**)&Qb, g_Q);
    cudaGetSymbolAddress((void**)&Kb, g_K);
    cudaGetSymbolAddress((void**)&Vb, g_V);
    cudaGetSymbolAddress((void**)&Ob, g_O);
    cudaGetSymbolAddress((void**)&Xt, g_Xt);
    cudaGetSymbolAddress((void**)&Ot, g_Ot);
    cudaGetSymbolAddress((void**)&Wqt, g_Wqt);
    cudaGetSymbolAddress((void**)&Wkt, g_Wkt);
    cudaGetSymbolAddress((void**)&Wvt, g_Wvt);
    cudaGetSymbolAddress((void**)&Wot, g_Wot);

    cudaFuncSetAttribute(flash_mma_kernel, cudaFuncAttributeMaxDynamicSharedMemorySize, FSM_BYTES);

    // tf32 rounding pre-pass
    {
        int n4;
        n4 = ROWS * HID / 4;
        cvt_tf32_kernel<<<(n4 + 255) / 256, 256>>>((const float4*)X, (float4*)Xt, n4);
        n4 = HID * HID / 4;
        cvt_tf32_kernel<<<(n4 + 255) / 256, 256>>>((const float4*)Wq, (float4*)Wqt, n4);
        n4 = HID * KVD / 4;
        cvt_tf32_kernel<<<(n4 + 255) / 256, 256>>>((const float4*)Wk, (float4*)Wkt, n4);
        cvt_tf32_kernel<<<(n4 + 255) / 256, 256>>>((const float4*)Wv, (float4*)Wvt, n4);
        n4 = HID * HID / 4;
        cvt_tf32_kernel<<<(n4 + 255) / 256, 256>>>((const float4*)Wo, (float4*)Wot, n4);
    }

    // QKV projections
    tf32_mma_gemm<<<dim3(HID / 128, ROWS / 128), 128>>>(Xt, Wqt, Qb, ROWS, HID, HID);
    tf32_mma_gemm<<<dim3(KVD / 128, ROWS / 128), 128>>>(Xt, Wkt, Kb, ROWS, KVD, HID);
    tf32_mma_gemm<<<dim3(KVD / 128, ROWS / 128), 128>>>(Xt, Wvt, Vb, ROWS, KVD, HID);

    // RoPE (rounds Q,K to tf32); round V in place
    {
        int totq = ROWS * NH * 64;
        rope_kernel<<<(totq + 255) / 256, 256>>>(Qb, NH);
        int totk = ROWS * NKV * 64;
        rope_kernel<<<(totk + 255) / 256, 256>>>(Kb, NKV);
        int n4 = ROWS * KVD / 4;
        cvt_tf32_kernel<<<(n4 + 255) / 256, 256>>>((const float4*)Vb, (float4*)Vb, n4);
    }

    // Flash attention (tf32 mma)
    flash_mma_kernel<<<dim3(SEQ / 128, NH, BSZ), 256, FSM_BYTES>>>(Qb, Kb, Vb, Ob);

    // Output projection
    {
        int n4 = ROWS * HID / 4;
        cvt_tf32_kernel<<<(n4 + 255) / 256, 256>>>((const float4*)Ob, (float4*)Ot, n4);
    }
    tf32_mma_gemm<<<dim3(HID / 128, ROWS / 128), 128>>>(Ot, Wot, out, ROWS, HID, HID);
}

// round 5
// speedup vs baseline: 4.0144x; 1.0020x over previous
#include <cuda_runtime.h>
#include <cuda_bf16.h>
#include <math.h>
#include <stdint.h>

// Problem constants
#define BSZ 2
#define SEQ 2048
#define HID 4096
#define NH  32
#define NKV 8
#define HD  128
#define ROWS (BSZ*SEQ)           // 4096
#define KVD (NKV*HD)             // 1024
#define KVSTR 2048               // packed K|V row stride

// ---------------- scratch ----------------
__device__ float g_Q[(size_t)ROWS * HID];
__device__ float g_KV[(size_t)ROWS * KVSTR];     // [row][K(1024) | V(1024)]
__device__ float g_O[(size_t)ROWS * HID];
__device__ float g_Xt[(size_t)ROWS * HID];
__device__ float g_Wqt[(size_t)HID * HID];
__device__ float g_Wkvt[(size_t)HID * KVSTR];    // packed Wk|Wv (tf32)
__device__ float g_Wot[(size_t)HID * HID];

__device__ __forceinline__ uint32_t smem_u32(const void* p) {
    uint32_t a;
    asm("{ .reg .u64 t; cvta.to.shared.u64 t, %1; cvt.u32.u64 %0, t; }" : "=r"(a) : "l"(p));
    return a;
}
__device__ __forceinline__ void cp16(uint32_t smem_addr, const void* gptr) {
    asm volatile("cp.async.cg.shared.global [%0], [%1], 16;" :: "r"(smem_addr), "l"(gptr) : "memory");
}
#define CP_COMMIT() asm volatile("cp.async.commit_group;" ::: "memory")
#define CP_WAIT(n)  asm volatile("cp.async.wait_group %0;" :: "n"(n) : "memory")

__device__ __forceinline__ uint32_t f2tf32(float f) {
    uint32_t u;
    asm("cvt.rna.tf32.f32 %0, %1;" : "=r"(u) : "f"(f));
    return u;
}
__device__ __forceinline__ void mma_tf32(float* c, uint32_t a0, uint32_t a1, uint32_t a2,
                                         uint32_t a3, uint32_t b0, uint32_t b1) {
    asm volatile(
        "mma.sync.aligned.m16n8k8.row.col.f32.tf32.tf32.f32 "
        "{%0,%1,%2,%3}, {%4,%5,%6,%7}, {%8,%9}, {%0,%1,%2,%3};"
        : "+f"(c[0]), "+f"(c[1]), "+f"(c[2]), "+f"(c[3])
        : "r"(a0), "r"(a1), "r"(a2), "r"(a3), "r"(b0), "r"(b1));
}

// ---------------- tf32 rounding passes ----------------
__global__ void cvt_tf32_kernel(const float4* __restrict__ in, float4* __restrict__ out, int n4) {
    int i = blockIdx.x * blockDim.x + threadIdx.x;
    if (i >= n4) return;
    float4 v = in[i];
    out[i] = make_float4(__uint_as_float(f2tf32(v.x)), __uint_as_float(f2tf32(v.y)),
                         __uint_as_float(f2tf32(v.z)), __uint_as_float(f2tf32(v.w)));
}
// pack [R][incols4*4] into out rows of stride4 at column offset off4
__global__ void cvt_pack_kernel(const float4* __restrict__ in, float4* __restrict__ out,
                                int n4, int incols4, int outstride4, int off4) {
    int i = blockIdx.x * blockDim.x + threadIdx.x;
    if (i >= n4) return;
    int row = i / incols4, col = i - row * incols4;
    float4 v = in[i];
    out[(size_t)row * outstride4 + off4 + col] =
        make_float4(__uint_as_float(f2tf32(v.x)), __uint_as_float(f2tf32(v.y)),
                    __uint_as_float(f2tf32(v.z)), __uint_as_float(f2tf32(v.w)));
}
// in-place strided rounding (for V region of packed KV)
__global__ void cvt_strided_kernel(float4* __restrict__ p, int n4, int cols4,
                                   int stride4, int off4) {
    int i = blockIdx.x * blockDim.x + threadIdx.x;
    if (i >= n4) return;
    int row = i / cols4, col = i - row * cols4;
    size_t idx = (size_t)row * stride4 + off4 + col;
    float4 v = p[idx];
    p[idx] = make_float4(__uint_as_float(f2tf32(v.x)), __uint_as_float(f2tf32(v.y)),
                         __uint_as_float(f2tf32(v.z)), __uint_as_float(f2tf32(v.w)));
}

// ================= tf32 mma GEMM: C[M,N] = A[M,K] @ B[K,N] =================
// 128x128 block, 128 threads (4 warps x 64x64), BK=16, 4-stage cp.async ring.
#define ASTR 20
#define BSTR 136
#define STG_A (128 * ASTR)
#define STG_B (16 * BSTR)
#define STG_FLOATS (STG_A + STG_B)          // 4736
#define GEMM_STAGES 4
#define GEMM_SMEM_BYTES (GEMM_STAGES * STG_FLOATS * 4)   // 75776

__global__ __launch_bounds__(128)
void tf32_mma_gemm(const float* __restrict__ A, const float* __restrict__ B,
                   float* __restrict__ C, int M, int N, int K) {
    extern __shared__ float smg[];
    const uint32_t smb = smem_u32(smg);

    const int tid = threadIdx.x;
    const int wid = tid >> 5;
    const int lid = tid & 31;
    const int gi = lid >> 2;
    const int qi = lid & 3;
    const int wm = (wid & 1) * 64;
    const int wn = (wid >> 1) * 64;

    const size_t bm = (size_t)blockIdx.y * 128;
    const size_t bn = (size_t)blockIdx.x * 128;
    const float* Ap = A + bm * K;
    const float* Bp = B + bn;

    const int aRow = tid >> 2;          // 0..31 (+32/iter)
    const int aCol = (tid & 3) * 4;
    const int bRow = tid >> 5;          // 0..3 (+4/iter)
    const int bCol = (tid & 31) * 4;

    float acc[4][8][4];
#pragma unroll
    for (int mt = 0; mt < 4; mt++)
#pragma unroll
        for (int nt = 0; nt < 8; nt++)
#pragma unroll
            for (int r = 0; r < 4; r++) acc[mt][nt][r] = 0.0f;

    auto load_stage = [&](int kstep, int slot) {
        uint32_t as = smb + (uint32_t)(slot * STG_FLOATS) * 4u;
        uint32_t bs = as + STG_A * 4u;
        const int k0 = kstep * 16;
#pragma unroll
        for (int r = 0; r < 4; r++) {
            int row = aRow + r * 32;
            cp16(as + (row * ASTR + aCol) * 4, Ap + (size_t)row * K + k0 + aCol);
        }
#pragma unroll
        for (int r = 0; r < 4; r++) {
            int row = bRow + r * 4;
            cp16(bs + (row * BSTR + bCol) * 4, Bp + (size_t)(k0 + row) * N + bCol);
        }
    };

    const int nsteps = K / 16;
#pragma unroll
    for (int s = 0; s < GEMM_STAGES - 1; s++) {
        if (s < nsteps) load_stage(s, s);
        CP_COMMIT();
    }

    for (int step = 0; step < nsteps; step++) {
        CP_WAIT(GEMM_STAGES - 2);
        __syncthreads();
        if (step + GEMM_STAGES - 1 < nsteps)
            load_stage(step + GEMM_STAGES - 1, (step + GEMM_STAGES - 1) & (GEMM_STAGES - 1));
        CP_COMMIT();

        const float* Ab = smg + (step & (GEMM_STAGES - 1)) * STG_FLOATS;
        const float* Bb = Ab + STG_A;
#pragma unroll
        for (int kk = 0; kk < 16; kk += 8) {
            uint32_t a[4][4], b[8][2];
#pragma unroll
            for (int mt = 0; mt < 4; mt++) {
                int r = wm + mt * 16 + gi;
                a[mt][0] = __float_as_uint(Ab[r * ASTR + kk + qi]);
                a[mt][1] = __float_as_uint(Ab[(r + 8) * ASTR + kk + qi]);
                a[mt][2] = __float_as_uint(Ab[r * ASTR + kk + qi + 4]);
                a[mt][3] = __float_as_uint(Ab[(r + 8) * ASTR + kk + qi + 4]);
            }
#pragma unroll
            for (int nt = 0; nt < 8; nt++) {
                int c = wn + nt * 8 + gi;
                b[nt][0] = __float_as_uint(Bb[(kk + qi) * BSTR + c]);
                b[nt][1] = __float_as_uint(Bb[(kk + qi + 4) * BSTR + c]);
            }
#pragma unroll
            for (int mt = 0; mt < 4; mt++)
#pragma unroll
                for (int nt = 0; nt < 8; nt++)
                    mma_tf32(acc[mt][nt], a[mt][0], a[mt][1], a[mt][2], a[mt][3],
                             b[nt][0], b[nt][1]);
        }
    }

#pragma unroll
    for (int mt = 0; mt < 4; mt++) {
#pragma unroll
        for (int nt = 0; nt < 8; nt++) {
            size_t row = bm + wm + mt * 16 + gi;
            size_t col = bn + wn + nt * 8 + qi * 2;
            *(float2*)&C[row * N + col] = make_float2(acc[mt][nt][0], acc[mt][nt][1]);
            *(float2*)&C[(row + 8) * N + col] = make_float2(acc[mt][nt][2], acc[mt][nt][3]);
        }
    }
}

// ---------------- RoPE (in-place, rounds output to tf32) ----------------
__global__ void rope_kernel(float* __restrict__ x, int nheads, int rowstride) {
    int idx = blockIdx.x * blockDim.x + threadIdx.x;
    int total = ROWS * nheads * 64;
    if (idx >= total) return;
    int d = idx & 63;
    int h = (idx >> 6) % nheads;
    int row = idx / (64 * nheads);
    int s = row & (SEQ - 1);
    float inv = 1.0f / powf(10000.0f, (2.0f * (float)d) / 128.0f);
    float ang = (float)s * inv;
    float sn, cs;
    sincosf(ang, &sn, &cs);
    size_t base = (size_t)row * rowstride + (size_t)h * HD;
    float x1 = x[base + d];
    float x2 = x[base + d + 64];
    x[base + d]      = __uint_as_float(f2tf32(x1 * cs - x2 * sn));
    x[base + d + 64] = __uint_as_float(f2tf32(x2 * cs + x1 * sn));
}

// ================= Flash attention (tf32 mma, causal, GQA) =================
// BQ=128, BC=64, 256 threads (8 warps, each owns 16 q-rows).
#define QSTR 132
#define KSTR 132
#define VSTR 136
#define SQ_OFF 0
#define SK0_OFF (128 * QSTR)
#define SK1_OFF (SK0_OFF + 64 * KSTR)
#define SV0_OFF (SK1_OFF + 64 * KSTR)
#define SV1_OFF (SV0_OFF + 64 * VSTR)
#define FSM_FLOATS (SV1_OFF + 64 * VSTR)
#define FSM_BYTES (FSM_FLOATS * 4)

__global__ __launch_bounds__(256)
void flash_mma_kernel(const float* __restrict__ Q, const float* __restrict__ KV,
                      float* __restrict__ O) {
    extern __shared__ float sm[];
    const int tid = threadIdx.x;
    const int wid = tid >> 5;
    const int lid = tid & 31;
    const int gi = lid >> 2;
    const int qi = lid & 3;
    const int wm = wid * 16;

    const int qt = blockIdx.x;
    const int h  = blockIdx.y;
    const int b  = blockIdx.z;
    const int kvh = h >> 2;
    const int q0 = qt * 128;

    const float* Qp = Q + (size_t)b * SEQ * HID + (size_t)h * HD;
    const float* Kp = KV + (size_t)b * SEQ * KVSTR + (size_t)kvh * HD;
    const float* Vp = Kp + KVD;   // V half of packed row
    float* Op = O + (size_t)b * SEQ * HID + (size_t)h * HD;

    const uint32_t smb = smem_u32(sm);

    for (int i = tid; i < 128 * 32; i += 256) {
        int row = i >> 5, c4 = (i & 31) * 4;
        *(float4*)&sm[SQ_OFF + row * QSTR + c4] =
            *(const float4*)&Qp[(size_t)(q0 + row) * HID + c4];
    }

    float m0 = -1e30f, m1 = -1e30f, l0 = 0.0f, l1 = 0.0f;
    float o[16][4];
#pragma unroll
    for (int f = 0; f < 16; f++)
#pragma unroll
        for (int r = 0; r < 4; r++) o[f][r] = 0.0f;

    const int ntiles = 2 * qt + 2;
    const float qscale = 0.08838834764831845f;

    {
        uint32_t kb = smb + SK0_OFF * 4;
        uint32_t vb = smb + SV0_OFF * 4;
        for (int i = tid; i < 64 * 32; i += 256) {
            int row = i >> 5, c4 = (i & 31) * 4;
            cp16(kb + (row * KSTR + c4) * 4, Kp + (size_t)row * KVSTR + c4);
            cp16(vb + (row * VSTR + c4) * 4, Vp + (size_t)row * KVSTR + c4);
        }
        CP_COMMIT();
    }

    for (int j = 0; j < ntiles; j++) {
        const int cur = j & 1;
        CP_WAIT(0);
        __syncthreads();

        if (j + 1 < ntiles) {
            const int nxt = (j + 1) & 1;
            uint32_t kb = smb + (nxt ? SK1_OFF : SK0_OFF) * 4;
            uint32_t vb = smb + (nxt ? SV1_OFF : SV0_OFF) * 4;
            const size_t r0 = (size_t)(j + 1) * 64;
            for (int i = tid; i < 64 * 32; i += 256) {
                int row = i >> 5, c4 = (i & 31) * 4;
                cp16(kb + (row * KSTR + c4) * 4, Kp + (r0 + row) * KVSTR + c4);
                cp16(vb + (row * VSTR + c4) * 4, Vp + (r0 + row) * KVSTR + c4);
            }
            CP_COMMIT();
        }

        const float* sK = sm + (cur ? SK1_OFF : SK0_OFF);
        const float* sV = sm + (cur ? SV1_OFF : SV0_OFF);
        const float* sQ = sm + SQ_OFF;

        float s[8][4];
#pragma unroll
        for (int nt = 0; nt < 8; nt++)
#pragma unroll
            for (int r = 0; r < 4; r++) s[nt][r] = 0.0f;

#pragma unroll
        for (int kk = 0; kk < 128; kk += 8) {
            uint32_t a0 = __float_as_uint(sQ[(wm + gi) * QSTR + kk + qi]);
            uint32_t a1 = __float_as_uint(sQ[(wm + gi + 8) * QSTR + kk + qi]);
            uint32_t a2 = __float_as_uint(sQ[(wm + gi) * QSTR + kk + qi + 4]);
            uint32_t a3 = __float_as_uint(sQ[(wm + gi + 8) * QSTR + kk + qi + 4]);
#pragma unroll
            for (int nt = 0; nt < 8; nt++) {
                uint32_t b0 = __float_as_uint(sK[(nt * 8 + gi) * KSTR + kk + qi]);
                uint32_t b1 = __float_as_uint(sK[(nt * 8 + gi) * KSTR + kk + qi + 4]);
                mma_tf32(s[nt], a0, a1, a2, a3, b0, b1);
            }
        }

        const int row0 = q0 + wm + gi;
        const int row1 = row0 + 8;
        const bool diag = (j >= 2 * qt);
#pragma unroll
        for (int nt = 0; nt < 8; nt++) {
#pragma unroll
            for (int r = 0; r < 4; r++) s[nt][r] *= qscale;
            if (diag) {
                int c = j * 64 + nt * 8 + 2 * qi;
                if (c > row0)     s[nt][0] = -1e30f;
                if (c + 1 > row0) s[nt][1] = -1e30f;
                if (c > row1)     s[nt][2] = -1e30f;
                if (c + 1 > row1) s[nt][3] = -1e30f;
            }
        }
        float mx0 = -1e30f, mx1 = -1e30f;
#pragma unroll
        for (int nt = 0; nt < 8; nt++) {
            mx0 = fmaxf(mx0, fmaxf(s[nt][0], s[nt][1]));
            mx1 = fmaxf(mx1, fmaxf(s[nt][2], s[nt][3]));
        }
        mx0 = fmaxf(mx0, __shfl_xor_sync(0xffffffffu, mx0, 1));
        mx0 = fmaxf(mx0, __shfl_xor_sync(0xffffffffu, mx0, 2));
        mx1 = fmaxf(mx1, __shfl_xor_sync(0xffffffffu, mx1, 1));
        mx1 = fmaxf(mx1, __shfl_xor_sync(0xffffffffu, mx1, 2));

        float mn0 = fmaxf(m0, mx0), mn1 = fmaxf(m1, mx1);
        float sc0 = __expf(m0 - mn0), sc1 = __expf(m1 - mn1);
        m0 = mn0; m1 = mn1;

        float rs0 = 0.0f, rs1 = 0.0f;
        uint32_t pu[8][4];
#pragma unroll
        for (int nt = 0; nt < 8; nt++) {
            float p0 = __expf(s[nt][0] - m0);
            float p1 = __expf(s[nt][1] - m0);
            float p2 = __expf(s[nt][2] - m1);
            float p3 = __expf(s[nt][3] - m1);
            rs0 += p0 + p1;
            rs1 += p2 + p3;
            pu[nt][0] = f2tf32(p0);
            pu[nt][1] = f2tf32(p1);
            pu[nt][2] = f2tf32(p2);
            pu[nt][3] = f2tf32(p3);
        }
        rs0 += __shfl_xor_sync(0xffffffffu, rs0, 1);
        rs0 += __shfl_xor_sync(0xffffffffu, rs0, 2);
        rs1 += __shfl_xor_sync(0xffffffffu, rs1, 1);
        rs1 += __shfl_xor_sync(0xffffffffu, rs1, 2);
        l0 = l0 * sc0 + rs0;
        l1 = l1 * sc1 + rs1;
#pragma unroll
        for (int f = 0; f < 16; f++) {
            o[f][0] *= sc0; o[f][1] *= sc0;
            o[f][2] *= sc1; o[f][3] *= sc1;
        }

        const int srcA = (gi << 2) + (qi >> 1);
        const int srcB = srcA + 2;
        const bool odd = (qi & 1);
#pragma unroll
        for (int kc = 0; kc < 8; kc++) {
            uint32_t x0 = __shfl_sync(0xffffffffu, pu[kc][0], srcA);
            uint32_t x1 = __shfl_sync(0xffffffffu, pu[kc][1], srcA);
            uint32_t y0 = __shfl_sync(0xffffffffu, pu[kc][0], srcB);
            uint32_t y1 = __shfl_sync(0xffffffffu, pu[kc][1], srcB);
            uint32_t x2 = __shfl_sync(0xffffffffu, pu[kc][2], srcA);
            uint32_t x3 = __shfl_sync(0xffffffffu, pu[kc][3], srcA);
            uint32_t y2 = __shfl_sync(0xffffffffu, pu[kc][2], srcB);
            uint32_t y3 = __shfl_sync(0xffffffffu, pu[kc][3], srcB);
            uint32_t a0 = odd ? x1 : x0;
            uint32_t a2 = odd ? y1 : y0;
            uint32_t a1 = odd ? x3 : x2;
            uint32_t a3 = odd ? y3 : y2;
#pragma unroll
            for (int nt2 = 0; nt2 < 16; nt2++) {
                uint32_t b0 = __float_as_uint(sV[(kc * 8 + qi) * VSTR + nt2 * 8 + gi]);
                uint32_t b1 = __float_as_uint(sV[(kc * 8 + qi + 4) * VSTR + nt2 * 8 + gi]);
                mma_tf32(o[nt2], a0, a1, a2, a3, b0, b1);
            }
        }
    }

    // epilogue (rounds to tf32 for the O-projection GEMM)
    const float inv0 = 1.0f / l0;
    const float inv1 = 1.0f / l1;
    const size_t r0 = (size_t)(q0 + wm + gi);
    const size_t r1 = r0 + 8;
#pragma unroll
    for (int nt2 = 0; nt2 < 16; nt2++) {
        int col = nt2 * 8 + 2 * qi;
        *(float2*)&Op[r0 * HID + col] = make_float2(
            __uint_as_float(f2tf32(o[nt2][0] * inv0)),
            __uint_as_float(f2tf32(o[nt2][1] * inv0)));
        *(float2*)&Op[r1 * HID + col] = make_float2(
            __uint_as_float(f2tf32(o[nt2][2] * inv1)),
            __uint_as_float(f2tf32(o[nt2][3] * inv1)));
    }
}

// ---------------- launch ----------------
extern "C" void kernel_launch(void* const* d_in, const int* in_sizes, int n_in,
                              void* d_out, int out_size) {
    (void)in_sizes; (void)n_in; (void)out_size;
    const float* X  = (const float*)d_in[0];
    const float* Wq = (const float*)d_in[3];
    const float* Wk = (const float*)d_in[4];
    const float* Wv = (const float*)d_in[5];
    const float* Wo = (const float*)d_in[6];
    float* out = (float*)d_out;

    float *Qb, *KVb, *Ob, *Xt, *Wqt, *Wkvt, *Wot;
    cudaGetSymbolAddress((void**)&Qb, g_Q);
    cudaGetSymbolAddress((void**)&KVb, g_KV);
    cudaGetSymbolAddress((void**)&Ob, g_O);
    cudaGetSymbolAddress((void**)&Xt, g_Xt);
    cudaGetSymbolAddress((void**)&Wqt, g_Wqt);
    cudaGetSymbolAddress((void**)&Wkvt, g_Wkvt);
    cudaGetSymbolAddress((void**)&Wot, g_Wot);

    cudaFuncSetAttribute(flash_mma_kernel, cudaFuncAttributeMaxDynamicSharedMemorySize, FSM_BYTES);
    cudaFuncSetAttribute(tf32_mma_gemm, cudaFuncAttributeMaxDynamicSharedMemorySize, GEMM_SMEM_BYTES);

    // tf32 rounding + weight packing
    {
        int n4;
        n4 = ROWS * HID / 4;
        cvt_tf32_kernel<<<(n4 + 255) / 256, 256>>>((const float4*)X, (float4*)Xt, n4);
        n4 = HID * HID / 4;
        cvt_tf32_kernel<<<(n4 + 255) / 256, 256>>>((const float4*)Wq, (float4*)Wqt, n4);
        cvt_tf32_kernel<<<(n4 + 255) / 256, 256>>>((const float4*)Wo, (float4*)Wot, n4);
        n4 = HID * KVD / 4;
        cvt_pack_kernel<<<(n4 + 255) / 256, 256>>>((const float4*)Wk, (float4*)Wkvt, n4,
                                                   KVD / 4, KVSTR / 4, 0);
        cvt_pack_kernel<<<(n4 + 255) / 256, 256>>>((const float4*)Wv, (float4*)Wkvt, n4,
                                                   KVD / 4, KVSTR / 4, KVD / 4);
    }

    // Projections: Q and fused K|V
    tf32_mma_gemm<<<dim3(HID / 128, ROWS / 128), 128, GEMM_SMEM_BYTES>>>(Xt, Wqt, Qb, ROWS, HID, HID);
    tf32_mma_gemm<<<dim3(KVSTR / 128, ROWS / 128), 128, GEMM_SMEM_BYTES>>>(Xt, Wkvt, KVb, ROWS, KVSTR, HID);

    // RoPE (rounds Q,K to tf32); round V region in place
    {
        int totq = ROWS * NH * 64;
        rope_kernel<<<(totq + 255) / 256, 256>>>(Qb, NH, HID);
        int totk = ROWS * NKV * 64;
        rope_kernel<<<(totk + 255) / 256, 256>>>(KVb, NKV, KVSTR);
        int n4 = ROWS * KVD / 4;
        cvt_strided_kernel<<<(n4 + 255) / 256, 256>>>((float4*)KVb, n4, KVD / 4,
                                                      KVSTR / 4, KVD / 4);
    }

    // Flash attention (tf32 mma), rounds its output
    flash_mma_kernel<<<dim3(SEQ / 128, NH, BSZ), 256, FSM_BYTES>>>(Qb, KVb, Ob);

    // Output projection
    tf32_mma_gemm<<<dim3(HID / 128, ROWS / 128), 128, GEMM_SMEM_BYTES>>>(Ob, Wot, out, ROWS, HID, HID);
}